// round 16
// baseline (speedup 1.0000x reference)
#include <cuda_runtime.h>
#include <math.h>
#include <stdint.h>
#include <stdio.h>

#define BB    32
#define LL    1024
#define BLROWS (BB*LL)          // 32768
#define HID   512
#define G4    2048
#define NUMC  1000
#define ATTD  80

// LSTM partition: 4 independent groups x 32 CTAs; each group owns 8 batches.
#define NGRP  4
#define GCTAS 32
#define GBATCH 8

// ---------------- scratch (static device globals: allocation-free) ----------
__device__ float g_sae  [(size_t)BLROWS * HID];    // LSTM input rows
__device__ float g_xpre [(size_t)BLROWS * G4];     // x @ W_ih^T + b
__device__ float g_hout [(size_t)BLROWS * HID];    // LSTM hidden states ("out")
__device__ float g_hx   [2][NGRP][HID * GBATCH];   // transposed h exchange [k][b], parity buffered
__device__ float g_attT [(size_t)BLROWS * ATTD];   // tanh(out @ mlp_W^T + b)
__device__ float g_att  [BLROWS];                  // per-position attention logit
__device__ float g_final[(size_t)BLROWS * (2*HID)];// [attn_cum_1, out]
__device__ unsigned g_cnt[NGRP * 32];              // per-group arrival counters (128B padded)
__device__ unsigned g_ph [NGRP * 32];              // per-group phases (128B padded)

// ---------------- embedding gather ------------------------------------------
__global__ void embed_kernel(const int* __restrict__ skill,
                             const int* __restrict__ answer,
                             const float* __restrict__ skill_table,
                             const float* __restrict__ answer_table)
{
    int idx = blockIdx.x * blockDim.x + threadIdx.x;   // over BLROWS*128 float4
    int row = idx >> 7;
    int q   = idx & 127;
    if (row >= BLROWS) return;
    int sk = skill[row];
    int an = answer[row];
    const float4* se = (const float4*)(skill_table  + (size_t)sk * 256);
    const float4* ae = (const float4*)(answer_table + (size_t)an * 256);
    float4 v;
    if (an == 1) v = (q < 64) ? se[q] : ae[q - 64];   // [skill, answer]
    else         v = (q < 64) ? ae[q] : se[q - 64];   // [answer, skill]
    ((float4*)g_sae)[(size_t)row * 128 + q] = v;
}

// ---------------- tf32 tensor-core GEMM: C = op(A @ B^T + bias1 + bias2) ----
__device__ __forceinline__ uint32_t f2tf32(float v) {
    uint32_t u;
    asm("cvt.rna.tf32.f32 %0, %1;" : "=r"(u) : "f"(v));
    return u;
}

template<int OP>
__global__ void __launch_bounds__(256)
tf32gemm_nt(const float* __restrict__ A, const float* __restrict__ Bm,
            const float* __restrict__ bias1, const float* __restrict__ bias2,
            float* __restrict__ C, int M, int N, int K)
{
    __shared__ uint32_t As[2][4096];
    __shared__ uint32_t Bs[2][4096];

    const int tid  = threadIdx.x;
    const int warp = tid >> 5;
    const int lane = tid & 31;
    const int wm   = warp >> 2;      // 0..1
    const int wn   = warp & 3;       // 0..3
    const int bm   = blockIdx.y * 128;
    const int bn   = blockIdx.x * 128;

    float acc[4][4][4];
    #pragma unroll
    for (int i = 0; i < 4; i++)
        #pragma unroll
        for (int j = 0; j < 4; j++)
            #pragma unroll
            for (int r = 0; r < 4; r++) acc[i][j][r] = 0.f;

    int rowc[4], kqc[4];
    #pragma unroll
    for (int ch = 0; ch < 4; ch++) {
        int idx = tid + ch * 256;
        rowc[ch] = idx >> 3;
        kqc[ch]  = idx & 7;
    }

    float4 ra[4], rb[4];

    #pragma unroll
    for (int ch = 0; ch < 4; ch++) {
        ra[ch] = *(const float4*)(A + (size_t)(bm + rowc[ch]) * K + kqc[ch] * 4);
        rb[ch] = make_float4(0.f, 0.f, 0.f, 0.f);
        if (bn + rowc[ch] < N)
            rb[ch] = *(const float4*)(Bm + (size_t)(bn + rowc[ch]) * K + kqc[ch] * 4);
    }
    #pragma unroll
    for (int ch = 0; ch < 4; ch++) {
        int row = rowc[ch], kq = kqc[ch];
        int ks = kq >> 1, khi = kq & 1;
        {
            int mt = row >> 4, mm = row & 15;
            uint32_t* dst = &As[0][((ks * 8 + mt) * 32 + (mm & 7) * 4) * 4 + khi * 2 + (mm >> 3)];
            dst[0]  = f2tf32(ra[ch].x); dst[4]  = f2tf32(ra[ch].y);
            dst[8]  = f2tf32(ra[ch].z); dst[12] = f2tf32(ra[ch].w);
        }
        {
            int nt = row >> 3, nn = row & 7;
            uint32_t* dst = &Bs[0][((ks * 16 + nt) * 32 + nn * 4) * 2 + khi];
            dst[0] = f2tf32(rb[ch].x); dst[2] = f2tf32(rb[ch].y);
            dst[4] = f2tf32(rb[ch].z); dst[6] = f2tf32(rb[ch].w);
        }
    }
    __syncthreads();

    const int nkt = K >> 5;
    for (int kt = 0; kt < nkt; kt++) {
        const int cur = kt & 1;
        if (kt + 1 < nkt) {
            int kofs = (kt + 1) * 32;
            #pragma unroll
            for (int ch = 0; ch < 4; ch++) {
                ra[ch] = *(const float4*)(A + (size_t)(bm + rowc[ch]) * K + kofs + kqc[ch] * 4);
                rb[ch] = make_float4(0.f, 0.f, 0.f, 0.f);
                if (bn + rowc[ch] < N)
                    rb[ch] = *(const float4*)(Bm + (size_t)(bn + rowc[ch]) * K + kofs + kqc[ch] * 4);
            }
        }

        #pragma unroll
        for (int ks = 0; ks < 4; ks++) {
            uint32_t af[4][4];
            uint32_t bf[4][2];
            #pragma unroll
            for (int mt = 0; mt < 4; mt++) {
                uint4 v = *(const uint4*)&As[cur][((ks * 8 + wm * 4 + mt) * 32 + lane) * 4];
                af[mt][0] = v.x; af[mt][1] = v.y; af[mt][2] = v.z; af[mt][3] = v.w;
            }
            #pragma unroll
            for (int nt = 0; nt < 4; nt++) {
                uint2 v = *(const uint2*)&Bs[cur][((ks * 16 + wn * 4 + nt) * 32 + lane) * 2];
                bf[nt][0] = v.x; bf[nt][1] = v.y;
            }
            #pragma unroll
            for (int mt = 0; mt < 4; mt++)
                #pragma unroll
                for (int nt = 0; nt < 4; nt++) {
                    asm volatile(
                        "mma.sync.aligned.m16n8k8.row.col.f32.tf32.tf32.f32 "
                        "{%0,%1,%2,%3}, {%4,%5,%6,%7}, {%8,%9}, {%0,%1,%2,%3};"
                        : "+f"(acc[mt][nt][0]), "+f"(acc[mt][nt][1]),
                          "+f"(acc[mt][nt][2]), "+f"(acc[mt][nt][3])
                        : "r"(af[mt][0]), "r"(af[mt][1]),
                          "r"(af[mt][2]), "r"(af[mt][3]),
                          "r"(bf[nt][0]), "r"(bf[nt][1]));
                }
        }

        if (kt + 1 < nkt) {
            const int nb = (kt + 1) & 1;
            #pragma unroll
            for (int ch = 0; ch < 4; ch++) {
                int row = rowc[ch], kq = kqc[ch];
                int ks = kq >> 1, khi = kq & 1;
                {
                    int mt = row >> 4, mm = row & 15;
                    uint32_t* dst = &As[nb][((ks * 8 + mt) * 32 + (mm & 7) * 4) * 4 + khi * 2 + (mm >> 3)];
                    dst[0]  = f2tf32(ra[ch].x); dst[4]  = f2tf32(ra[ch].y);
                    dst[8]  = f2tf32(ra[ch].z); dst[12] = f2tf32(ra[ch].w);
                }
                {
                    int nt = row >> 3, nn = row & 7;
                    uint32_t* dst = &Bs[nb][((ks * 16 + nt) * 32 + nn * 4) * 2 + khi];
                    dst[0] = f2tf32(rb[ch].x); dst[2] = f2tf32(rb[ch].y);
                    dst[4] = f2tf32(rb[ch].z); dst[6] = f2tf32(rb[ch].w);
                }
            }
        }
        __syncthreads();
    }

    #pragma unroll
    for (int mt = 0; mt < 4; mt++) {
        int r0 = bm + wm * 64 + mt * 16 + (lane >> 2);
        #pragma unroll
        for (int nt = 0; nt < 4; nt++) {
            int c0 = bn + wn * 32 + nt * 8 + (lane & 3) * 2;
            if (c0 >= N) continue;            // N is even, pair is safe
            float bsum = 0.f;
            float bsum1 = 0.f;
            if (bias1) { bsum += bias1[c0]; bsum1 += bias1[c0 + 1]; }
            if (bias2) { bsum += bias2[c0]; bsum1 += bias2[c0 + 1]; }
            #pragma unroll
            for (int half = 0; half < 2; half++) {
                int row = r0 + half * 8;
                float v0 = acc[mt][nt][half * 2 + 0] + bsum;
                float v1 = acc[mt][nt][half * 2 + 1] + bsum1;
                if (OP == 1)      { v0 = tanhf(v0); v1 = tanhf(v1); }
                else if (OP == 2) { v0 = 1.f / (1.f + expf(-v0));
                                    v1 = 1.f / (1.f + expf(-v1)); }
                *(float2*)(C + (size_t)row * N + c0) = make_float2(v0, v1);
            }
        }
    }
}

// ---------------- persistent LSTM v3: 4 groups x 32 CTAs --------------------
// Group g owns batches [g*8, g*8+8) and ALL 2048 gate rows (64 rows/CTA,
// W slice 133KB SMEM-resident). Groups are fully independent: per-group
// barrier (32 arrivals) and per-group transposed h exchange buffer.
// Warp layout: 16 rows x 2 batch-groups, fixed k-half per warp-half.
__global__ void __launch_bounds__(256)
lstm_kernel(const float* __restrict__ xpre, const float* __restrict__ W_hh,
            float* __restrict__ hout)
{
    extern __shared__ float sm[];
    float* W_s = sm;                   // 64 rows x 520 (padded)
    float* h_s = sm + 64 * 520;        // [k][b]: 512 x 8
    __shared__ float gps[2][GBATCH][68];  // partial gate sums per k-half

    const int tid  = threadIdx.x;
    const int grp  = blockIdx.x >> 5;       // 0..3
    const int cig  = blockIdx.x & 31;       // CTA within group
    const int w    = tid >> 5;
    const int lane = tid & 31;
    const int r16  = lane & 15;
    const int bg   = lane >> 4;              // 0..1 (batches bg*4..bg*4+3)
    const int kh   = w >> 2;                 // k-half
    const int row  = (w & 3) * 16 + r16;     // 0..63 = gate*16 + unit

    // epilogue identity (threads 0..127): batch eb (0..7), unit eu (0..15)
    const int eb = tid >> 4, eu = tid & 15;
    float c_reg = 0.f;

    // load W_hh slice once: local row rr = gate*16 + unit
    for (int i = tid; i < 64 * 512; i += 256) {
        int rr = i >> 9, kk = i & 511;
        int gr = (rr >> 4) * 512 + cig * 16 + (rr & 15);
        W_s[rr * 520 + kk] = W_hh[(size_t)gr * 512 + kk];
    }
    __syncthreads();

    const float4* Wp = (const float4*)(W_s + row * 520 + kh * 256);
    const float*  Hp = h_s + kh * 256 * 8 + bg * 4;

    unsigned* cntp = &g_cnt[grp * 32];
    volatile unsigned* php = (volatile unsigned*)&g_ph[grp * 32];

    for (int t = 0; t < LL; t++) {
        if (t > 0) {
            // stage h(t-1): 16KB transposed [k][8] copy from L2
            const float4* src = (const float4*)&g_hx[(t - 1) & 1][grp][0];
            float4* dst = (float4*)h_s;
            #pragma unroll
            for (int i = 0; i < 4; i++)
                dst[tid + i * 256] = __ldcg(src + tid + i * 256);
        }
        __syncthreads();

        // prefetch xpre for epilogue (latency hidden under FFMA phase)
        float xp0 = 0.f, xp1 = 0.f, xp2 = 0.f, xp3 = 0.f;
        if (tid < 128) {
            const float* xb = xpre + ((size_t)(grp * GBATCH + eb) * LL + t) * G4 + cig * 16 + eu;
            xp0 = __ldg(xb);        xp1 = __ldg(xb + 512);
            xp2 = __ldg(xb + 1024); xp3 = __ldg(xb + 1536);
        }

        float4 acc = make_float4(0.f, 0.f, 0.f, 0.f);
        if (t > 0) {
            #pragma unroll 4
            for (int kq = 0; kq < 64; kq++) {
                float4 wv = Wp[kq];
                const float* hb = Hp + kq * 32;   // 4 consecutive k, each 8 wide
                float4 h0 = *(const float4*)(hb);
                float4 h1 = *(const float4*)(hb + 8);
                float4 h2 = *(const float4*)(hb + 16);
                float4 h3 = *(const float4*)(hb + 24);
                acc.x += wv.x * h0.x; acc.y += wv.x * h0.y;
                acc.z += wv.x * h0.z; acc.w += wv.x * h0.w;
                acc.x += wv.y * h1.x; acc.y += wv.y * h1.y;
                acc.z += wv.y * h1.z; acc.w += wv.y * h1.w;
                acc.x += wv.z * h2.x; acc.y += wv.z * h2.y;
                acc.z += wv.z * h2.z; acc.w += wv.z * h2.w;
                acc.x += wv.w * h3.x; acc.y += wv.w * h3.y;
                acc.z += wv.w * h3.z; acc.w += wv.w * h3.w;
            }
        }
        gps[kh][bg * 4 + 0][row] = acc.x;
        gps[kh][bg * 4 + 1][row] = acc.y;
        gps[kh][bg * 4 + 2][row] = acc.z;
        gps[kh][bg * 4 + 3][row] = acc.w;
        __syncthreads();

        if (tid < 128) {
            float gi = gps[0][eb][eu]      + gps[1][eb][eu]      + xp0;
            float gf = gps[0][eb][16 + eu] + gps[1][eb][16 + eu] + xp1;
            float gc = gps[0][eb][32 + eu] + gps[1][eb][32 + eu] + xp2;
            float go = gps[0][eb][48 + eu] + gps[1][eb][48 + eu] + xp3;
            float i_ = 1.f / (1.f + expf(-gi));
            float f_ = 1.f / (1.f + expf(-gf));
            float gg = tanhf(gc);
            float o_ = 1.f / (1.f + expf(-go));
            c_reg = f_ * c_reg + i_ * gg;
            float hv = o_ * tanhf(c_reg);
            g_hx[t & 1][grp][(cig * 16 + eu) * GBATCH + eb] = hv;
            hout[((size_t)(grp * GBATCH + eb) * LL + t) * HID + cig * 16 + eu] = hv;
        }

        // ---- per-group barrier (32 arrivals, single level) ----
        __threadfence();
        __syncthreads();
        if (tid == 0) {
            unsigned ph = *php;
            if (atomicAdd(cntp, 1u) == (GCTAS - 1u)) {
                *cntp = 0u;
                __threadfence();
                *php = ph + 1u;
            } else {
                while (*php == ph) { __nanosleep(16); }
            }
        }
        __syncthreads();
    }
}

// ---------------- att[m] = attT[m,:] . sim_W --------------------------------
__global__ void att_reduce(const float* __restrict__ attT,
                           const float* __restrict__ simW,
                           float* __restrict__ att)
{
    int gid  = blockIdx.x * blockDim.x + threadIdx.x;
    int row  = gid >> 5;
    int lane = threadIdx.x & 31;
    if (row >= BLROWS) return;
    float v = 0.f;
    for (int a = lane; a < ATTD; a += 32)
        v += attT[(size_t)row * ATTD + a] * simW[a];
    #pragma unroll
    for (int o = 16; o; o >>= 1) v += __shfl_down_sync(0xffffffffu, v, o);
    if (lane == 0) att[row] = v;
}

// ---------------- causal attention via online-softmax prefix scan -----------
// grid (BB, 4), block 128: CTA handles batch b, h-chunk of 128.
__global__ void attn_scan(const float* __restrict__ att,
                          const float* __restrict__ out,
                          float* __restrict__ finalbuf)
{
    int b = blockIdx.x;
    int h = blockIdx.y * 128 + threadIdx.x;
    __shared__ float s_att[LL];
    for (int i = threadIdx.x; i < LL; i += 128) s_att[i] = att[(size_t)b * LL + i];
    __syncthreads();

    const float* ob = out      + (size_t)b * LL * HID + h;
    float*       fb = finalbuf + (size_t)b * LL * (2 * HID) + h;

    float m = -1e30f, den = 0.f, num = 0.f, cum = 0.f;
    for (int i = 0; i < LL; i++) {
        float s     = s_att[i];
        float mnew  = fmaxf(m, s);
        float scale = expf(m - mnew);
        float alpha = expf(s - mnew);
        float ov    = ob[(size_t)i * HID];
        num = num * scale + alpha * ov;
        den = den * scale + alpha;
        m   = mnew;
        fb[(size_t)i * (2 * HID)]       = cum;   // attn_cum_1 (exclusive)
        fb[(size_t)i * (2 * HID) + HID] = ov;    // out
        cum += num / den;
    }
}

// ---------------- launch -----------------------------------------------------
extern "C" void kernel_launch(void* const* d_in, const int* in_sizes, int n_in,
                              void* d_out, int out_size)
{
    const int*   skill        = (const int*)  d_in[0];
    const int*   answer       = (const int*)  d_in[1];
    const float* skill_table  = (const float*)d_in[2];
    const float* answer_table = (const float*)d_in[3];
    const float* W_ih         = (const float*)d_in[4];
    const float* W_hh         = (const float*)d_in[5];
    const float* b_ih         = (const float*)d_in[6];
    const float* b_hh         = (const float*)d_in[7];
    const float* mlp_W        = (const float*)d_in[8];
    const float* mlp_b        = (const float*)d_in[9];
    const float* sim_W        = (const float*)d_in[10];
    const float* fc_W         = (const float*)d_in[11];
    const float* fc_b         = (const float*)d_in[12];
    float* outp = (float*)d_out;

    float *p_sae, *p_xpre, *p_hout, *p_attT, *p_att, *p_final;
    cudaGetSymbolAddress((void**)&p_sae,   g_sae);
    cudaGetSymbolAddress((void**)&p_xpre,  g_xpre);
    cudaGetSymbolAddress((void**)&p_hout,  g_hout);
    cudaGetSymbolAddress((void**)&p_attT,  g_attT);
    cudaGetSymbolAddress((void**)&p_att,   g_att);
    cudaGetSymbolAddress((void**)&p_final, g_final);

    // 1) embeddings -> sae
    {
        int total = BLROWS * 128;
        embed_kernel<<<total / 256, 256>>>(skill, answer, skill_table, answer_table);
    }

    // 2) x_pre = sae @ W_ih^T + (b_ih + b_hh)      [tf32 tensor cores]
    {
        dim3 grid(G4 / 128, BLROWS / 128);
        tf32gemm_nt<0><<<grid, 256>>>(p_sae, W_ih, b_ih, b_hh, p_xpre,
                                      BLROWS, G4, HID);
    }

    // 3) LSTM recurrence (4 independent groups of 32 CTAs)
    {
        const int smem = (64 * 520 + 512 * GBATCH) * (int)sizeof(float);  // 149504
        cudaFuncSetAttribute(lstm_kernel,
                             cudaFuncAttributeMaxDynamicSharedMemorySize, smem);
        lstm_kernel<<<NGRP * GCTAS, 256, smem>>>(p_xpre, W_hh, p_hout);
    }

    // 4) attT = tanh(out @ mlp_W^T + mlp_b)        [tf32 tensor cores]
    {
        dim3 grid((ATTD + 127) / 128, BLROWS / 128);
        tf32gemm_nt<1><<<grid, 256>>>(p_hout, mlp_W, mlp_b, nullptr, p_attT,
                                      BLROWS, ATTD, HID);
    }

    // 5) att = attT . sim_W
    att_reduce<<<(BLROWS * 32) / 256, 256>>>(p_attT, sim_W, p_att);

    // 6) online-softmax prefix scan -> final = [attn_cum_1, out]
    {
        dim3 grid(BB, 4);
        attn_scan<<<grid, 128>>>(p_att, p_hout, p_final);
    }

    // 7) res = sigmoid(final @ fc_W^T + fc_b)      [tf32 tensor cores]
    {
        dim3 grid((NUMC + 127) / 128, BLROWS / 128);
        tf32gemm_nt<2><<<grid, 256>>>(p_final, fc_W, fc_b, nullptr, outp,
                                      BLROWS, NUMC, 2 * HID);
    }
}

// round 17
// speedup vs baseline: 1.1065x; 1.1065x over previous
#include <cuda_runtime.h>
#include <math.h>
#include <stdint.h>
#include <stdio.h>

#define BB    32
#define LL    1024
#define BLROWS (BB*LL)          // 32768
#define HID   512
#define G4    2048
#define NUMC  1000
#define ATTD  80

// LSTM partition: 4 independent groups x 32 CTAs; each group owns 8 batches.
#define NGRP  4
#define GCTAS 32
#define GBATCH 8

// ---------------- scratch (static device globals: allocation-free) ----------
__device__ float g_sae  [(size_t)BLROWS * HID];    // LSTM input rows
__device__ float g_xpre [(size_t)BLROWS * G4];     // x @ W_ih^T + b
__device__ float g_hout [(size_t)BLROWS * HID];    // LSTM hidden states ("out")
__device__ float g_hx   [2][NGRP][HID * GBATCH];   // transposed h exchange [k][b], parity buffered
__device__ float g_attT [(size_t)BLROWS * ATTD];   // tanh(out @ mlp_W^T + b)
__device__ float g_att  [BLROWS];                  // per-position attention logit
__device__ float g_final[(size_t)BLROWS * (2*HID)];// [attn_cum_1, out]
__device__ unsigned g_cnt[NGRP * 32];              // per-group arrival counters (128B padded)
__device__ unsigned g_ph [NGRP * 32];              // per-group phases (128B padded)

// ---------------- f32x2 / memory-order helpers -------------------------------
__device__ __forceinline__ unsigned long long dup2(float x) {
    unsigned long long r;
    unsigned u = __float_as_uint(x);
    asm("mov.b64 %0, {%1, %1};" : "=l"(r) : "r"(u));
    return r;
}
__device__ __forceinline__ void fma2(unsigned long long& acc,
                                     unsigned long long a, unsigned long long b) {
    asm("fma.rn.f32x2 %0, %1, %2, %0;" : "+l"(acc) : "l"(a), "l"(b));
}
__device__ __forceinline__ void add2(unsigned long long& a, unsigned long long b) {
    asm("add.rn.f32x2 %0, %0, %1;" : "+l"(a) : "l"(b));
}
__device__ __forceinline__ unsigned atom_add_release(unsigned* p, unsigned v) {
    unsigned old;
    asm volatile("atom.release.gpu.global.add.u32 %0, [%1], %2;"
                 : "=r"(old) : "l"(p), "r"(v) : "memory");
    return old;
}
__device__ __forceinline__ unsigned ld_acquire(const unsigned* p) {
    unsigned v;
    asm volatile("ld.acquire.gpu.global.u32 %0, [%1];" : "=r"(v) : "l"(p) : "memory");
    return v;
}
__device__ __forceinline__ void st_release(unsigned* p, unsigned v) {
    asm volatile("st.release.gpu.global.u32 [%0], %1;" :: "l"(p), "r"(v) : "memory");
}

// ---------------- embedding gather (+ LSTM barrier reset) --------------------
__global__ void embed_kernel(const int* __restrict__ skill,
                             const int* __restrict__ answer,
                             const float* __restrict__ skill_table,
                             const float* __restrict__ answer_table)
{
    if (blockIdx.x == 0 && threadIdx.x < NGRP) {   // reset barrier state each launch
        g_cnt[threadIdx.x * 32] = 0u;
        g_ph [threadIdx.x * 32] = 0u;
    }
    int idx = blockIdx.x * blockDim.x + threadIdx.x;   // over BLROWS*128 float4
    int row = idx >> 7;
    int q   = idx & 127;
    if (row >= BLROWS) return;
    int sk = skill[row];
    int an = answer[row];
    const float4* se = (const float4*)(skill_table  + (size_t)sk * 256);
    const float4* ae = (const float4*)(answer_table + (size_t)an * 256);
    float4 v;
    if (an == 1) v = (q < 64) ? se[q] : ae[q - 64];   // [skill, answer]
    else         v = (q < 64) ? ae[q] : se[q - 64];   // [answer, skill]
    ((float4*)g_sae)[(size_t)row * 128 + q] = v;
}

// ---------------- tf32 tensor-core GEMM: C = op(A @ B^T + bias1 + bias2) ----
__device__ __forceinline__ uint32_t f2tf32(float v) {
    uint32_t u;
    asm("cvt.rna.tf32.f32 %0, %1;" : "=r"(u) : "f"(v));
    return u;
}

template<int OP>
__global__ void __launch_bounds__(256)
tf32gemm_nt(const float* __restrict__ A, const float* __restrict__ Bm,
            const float* __restrict__ bias1, const float* __restrict__ bias2,
            float* __restrict__ C, int M, int N, int K)
{
    __shared__ uint32_t As[2][4096];
    __shared__ uint32_t Bs[2][4096];

    const int tid  = threadIdx.x;
    const int warp = tid >> 5;
    const int lane = tid & 31;
    const int wm   = warp >> 2;      // 0..1
    const int wn   = warp & 3;       // 0..3
    const int bm   = blockIdx.y * 128;
    const int bn   = blockIdx.x * 128;

    float acc[4][4][4];
    #pragma unroll
    for (int i = 0; i < 4; i++)
        #pragma unroll
        for (int j = 0; j < 4; j++)
            #pragma unroll
            for (int r = 0; r < 4; r++) acc[i][j][r] = 0.f;

    int rowc[4], kqc[4];
    #pragma unroll
    for (int ch = 0; ch < 4; ch++) {
        int idx = tid + ch * 256;
        rowc[ch] = idx >> 3;
        kqc[ch]  = idx & 7;
    }

    float4 ra[4], rb[4];

    #pragma unroll
    for (int ch = 0; ch < 4; ch++) {
        ra[ch] = *(const float4*)(A + (size_t)(bm + rowc[ch]) * K + kqc[ch] * 4);
        rb[ch] = make_float4(0.f, 0.f, 0.f, 0.f);
        if (bn + rowc[ch] < N)
            rb[ch] = *(const float4*)(Bm + (size_t)(bn + rowc[ch]) * K + kqc[ch] * 4);
    }
    #pragma unroll
    for (int ch = 0; ch < 4; ch++) {
        int row = rowc[ch], kq = kqc[ch];
        int ks = kq >> 1, khi = kq & 1;
        {
            int mt = row >> 4, mm = row & 15;
            uint32_t* dst = &As[0][((ks * 8 + mt) * 32 + (mm & 7) * 4) * 4 + khi * 2 + (mm >> 3)];
            dst[0]  = f2tf32(ra[ch].x); dst[4]  = f2tf32(ra[ch].y);
            dst[8]  = f2tf32(ra[ch].z); dst[12] = f2tf32(ra[ch].w);
        }
        {
            int nt = row >> 3, nn = row & 7;
            uint32_t* dst = &Bs[0][((ks * 16 + nt) * 32 + nn * 4) * 2 + khi];
            dst[0] = f2tf32(rb[ch].x); dst[2] = f2tf32(rb[ch].y);
            dst[4] = f2tf32(rb[ch].z); dst[6] = f2tf32(rb[ch].w);
        }
    }
    __syncthreads();

    const int nkt = K >> 5;
    for (int kt = 0; kt < nkt; kt++) {
        const int cur = kt & 1;
        if (kt + 1 < nkt) {
            int kofs = (kt + 1) * 32;
            #pragma unroll
            for (int ch = 0; ch < 4; ch++) {
                ra[ch] = *(const float4*)(A + (size_t)(bm + rowc[ch]) * K + kofs + kqc[ch] * 4);
                rb[ch] = make_float4(0.f, 0.f, 0.f, 0.f);
                if (bn + rowc[ch] < N)
                    rb[ch] = *(const float4*)(Bm + (size_t)(bn + rowc[ch]) * K + kofs + kqc[ch] * 4);
            }
        }

        #pragma unroll
        for (int ks = 0; ks < 4; ks++) {
            uint32_t af[4][4];
            uint32_t bf[4][2];
            #pragma unroll
            for (int mt = 0; mt < 4; mt++) {
                uint4 v = *(const uint4*)&As[cur][((ks * 8 + wm * 4 + mt) * 32 + lane) * 4];
                af[mt][0] = v.x; af[mt][1] = v.y; af[mt][2] = v.z; af[mt][3] = v.w;
            }
            #pragma unroll
            for (int nt = 0; nt < 4; nt++) {
                uint2 v = *(const uint2*)&Bs[cur][((ks * 16 + wn * 4 + nt) * 32 + lane) * 2];
                bf[nt][0] = v.x; bf[nt][1] = v.y;
            }
            #pragma unroll
            for (int mt = 0; mt < 4; mt++)
                #pragma unroll
                for (int nt = 0; nt < 4; nt++) {
                    asm volatile(
                        "mma.sync.aligned.m16n8k8.row.col.f32.tf32.tf32.f32 "
                        "{%0,%1,%2,%3}, {%4,%5,%6,%7}, {%8,%9}, {%0,%1,%2,%3};"
                        : "+f"(acc[mt][nt][0]), "+f"(acc[mt][nt][1]),
                          "+f"(acc[mt][nt][2]), "+f"(acc[mt][nt][3])
                        : "r"(af[mt][0]), "r"(af[mt][1]),
                          "r"(af[mt][2]), "r"(af[mt][3]),
                          "r"(bf[nt][0]), "r"(bf[nt][1]));
                }
        }

        if (kt + 1 < nkt) {
            const int nb = (kt + 1) & 1;
            #pragma unroll
            for (int ch = 0; ch < 4; ch++) {
                int row = rowc[ch], kq = kqc[ch];
                int ks = kq >> 1, khi = kq & 1;
                {
                    int mt = row >> 4, mm = row & 15;
                    uint32_t* dst = &As[nb][((ks * 8 + mt) * 32 + (mm & 7) * 4) * 4 + khi * 2 + (mm >> 3)];
                    dst[0]  = f2tf32(ra[ch].x); dst[4]  = f2tf32(ra[ch].y);
                    dst[8]  = f2tf32(ra[ch].z); dst[12] = f2tf32(ra[ch].w);
                }
                {
                    int nt = row >> 3, nn = row & 7;
                    uint32_t* dst = &Bs[nb][((ks * 16 + nt) * 32 + nn * 4) * 2 + khi];
                    dst[0] = f2tf32(rb[ch].x); dst[2] = f2tf32(rb[ch].y);
                    dst[4] = f2tf32(rb[ch].z); dst[6] = f2tf32(rb[ch].w);
                }
            }
        }
        __syncthreads();
    }

    #pragma unroll
    for (int mt = 0; mt < 4; mt++) {
        int r0 = bm + wm * 64 + mt * 16 + (lane >> 2);
        #pragma unroll
        for (int nt = 0; nt < 4; nt++) {
            int c0 = bn + wn * 32 + nt * 8 + (lane & 3) * 2;
            if (c0 >= N) continue;            // N is even, pair is safe
            float bsum = 0.f;
            float bsum1 = 0.f;
            if (bias1) { bsum += bias1[c0]; bsum1 += bias1[c0 + 1]; }
            if (bias2) { bsum += bias2[c0]; bsum1 += bias2[c0 + 1]; }
            #pragma unroll
            for (int half = 0; half < 2; half++) {
                int row = r0 + half * 8;
                float v0 = acc[mt][nt][half * 2 + 0] + bsum;
                float v1 = acc[mt][nt][half * 2 + 1] + bsum1;
                if (OP == 1)      { v0 = tanhf(v0); v1 = tanhf(v1); }
                else if (OP == 2) { v0 = 1.f / (1.f + expf(-v0));
                                    v1 = 1.f / (1.f + expf(-v1)); }
                *(float2*)(C + (size_t)row * N + c0) = make_float2(v0, v1);
            }
        }
    }
}

// ---------------- persistent LSTM v4: f32x2 + register blocking -------------
// 4 groups x 32 CTAs; CTA owns 64 gate rows x 8 batches x 512 k.
// 8 warps = 2 rowgroups(32) x 4 k-quarters(128). Lane: rs=lane>>2 (4-row
// chunk), ksl=lane&3 (32-k slice). Thread: 4 rows x 8 batches x 32 k, f32x2
// accumulators over batch pairs. W and h SMEM are XOR-bank-swizzled so every
// LDS.128 is conflict-free. k-quarter partials via u64 shfl + add.f32x2.
// Barrier: atom.add.release + ld.acquire poll by all threads.
__global__ void __launch_bounds__(256)
lstm_kernel(const float* __restrict__ xpre, const float* __restrict__ W_hh,
            float* __restrict__ hout)
{
    extern __shared__ float sm[];
    float* W_s = sm;                    // 64 rows x 520 floats, chunk-swizzled
    float* h_s = sm + 64 * 520;         // 512 x 8 [k][b], chunk-swizzled
    __shared__ float gps[4][64][10];    // k-quarter partials [q][row][b]

    const int tid  = threadIdx.x;
    const int grp  = blockIdx.x >> 5;        // 0..3
    const int cig  = blockIdx.x & 31;        // CTA within group
    const int w    = tid >> 5;
    const int lane = tid & 31;
    const int wr   = w & 1;                  // rowgroup (32 rows)
    const int wq   = w >> 1;                 // k-quarter (128 k)
    const int rs   = lane >> 2;              // 4-row chunk 0..7
    const int ksl  = lane & 3;               // 32-k slice
    const int rbase = wr * 32 + rs * 4;      // first of this thread's 4 rows
    const int kb    = wq * 128 + ksl * 32;   // first k

    // epilogue identity (threads 0..127): batch eb (0..7), unit eu (0..15)
    const int eb = tid >> 4, eu = tid & 15;
    float c_reg = 0.f;

    // load W_hh slice once (row-major, 520 stride, XOR swizzle on 16B chunks:
    // chunk ^= ((row>>2)&7) so the 8 rs-chunks of a warp hit 8 bank groups)
    for (int i = tid; i < 64 * 512; i += 256) {
        int rr = i >> 9, kk = i & 511;
        int gr = (rr >> 4) * 512 + cig * 16 + (rr & 15);
        int kf = (kk & ~3) ^ (((rr >> 2) & 7) << 2);
        W_s[rr * 520 + kf + (kk & 3)] = W_hh[(size_t)gr * 512 + kk];
    }
    __syncthreads();

    unsigned* cntp = &g_cnt[grp * 32];
    unsigned* php  = &g_ph [grp * 32];

    const float* Wrow = W_s + rbase * 520;

    for (int t = 0; t < LL; t++) {
        if (t > 0) {
            // stage h(t-1): 16KB copy, swizzled: chunk c -> c ^ ((c>>6)&3)
            const float4* src = (const float4*)&g_hx[(t - 1) & 1][grp][0];
            #pragma unroll
            for (int i = 0; i < 4; i++) {
                int c = tid + i * 256;
                ((float4*)h_s)[c ^ ((c >> 6) & 3)] = __ldcg(src + c);
            }
        }
        __syncthreads();

        // prefetch xpre for epilogue (hidden under compute)
        float xp0 = 0.f, xp1 = 0.f, xp2 = 0.f, xp3 = 0.f;
        if (tid < 128) {
            const float* xb = xpre + ((size_t)(grp * GBATCH + eb) * LL + t) * G4 + cig * 16 + eu;
            xp0 = __ldg(xb);        xp1 = __ldg(xb + 512);
            xp2 = __ldg(xb + 1024); xp3 = __ldg(xb + 1536);
        }

        unsigned long long acc[4][4];
        #pragma unroll
        for (int i = 0; i < 4; i++)
            #pragma unroll
            for (int p = 0; p < 4; p++) acc[i][p] = 0ull;

        if (t > 0) {
            #pragma unroll 2
            for (int kq = 0; kq < 8; kq++) {
                int k0 = kb + kq * 4;
                int ksw = k0 ^ (((rbase >> 2) & 7) << 2);   // W swizzle (const per thread)
                float wreg[4][4];
                *(float4*)wreg[0] = *(const float4*)(Wrow +          ksw);
                *(float4*)wreg[1] = *(const float4*)(Wrow + 1 * 520 + ksw);
                *(float4*)wreg[2] = *(const float4*)(Wrow + 2 * 520 + ksw);
                *(float4*)wreg[3] = *(const float4*)(Wrow + 3 * 520 + ksw);
                #pragma unroll
                for (int j = 0; j < 4; j++) {
                    int k = k0 + j;
                    int c0 = (k * 2)     ^ ksl;              // h swizzle
                    int c1 = (k * 2 + 1) ^ ksl;
                    unsigned long long hA0 = *(const unsigned long long*)(h_s + c0 * 4);
                    unsigned long long hA1 = *(const unsigned long long*)(h_s + c0 * 4 + 2);
                    unsigned long long hB0 = *(const unsigned long long*)(h_s + c1 * 4);
                    unsigned long long hB1 = *(const unsigned long long*)(h_s + c1 * 4 + 2);
                    #pragma unroll
                    for (int i = 0; i < 4; i++) {
                        unsigned long long d = dup2(wreg[i][j]);
                        fma2(acc[i][0], d, hA0);
                        fma2(acc[i][1], d, hA1);
                        fma2(acc[i][2], d, hB0);
                        fma2(acc[i][3], d, hB1);
                    }
                }
            }
        }

        // reduce over the 4 ksl lanes (lane bits 0,1)
        #pragma unroll
        for (int i = 0; i < 4; i++)
            #pragma unroll
            for (int p = 0; p < 4; p++) {
                unsigned long long v = acc[i][p];
                add2(v, __shfl_xor_sync(0xffffffffu, v, 1));
                add2(v, __shfl_xor_sync(0xffffffffu, v, 2));
                acc[i][p] = v;
            }
        if (ksl == 0) {
            #pragma unroll
            for (int i = 0; i < 4; i++)
                #pragma unroll
                for (int p = 0; p < 4; p++)
                    *(unsigned long long*)&gps[wq][rbase + i][p * 2] = acc[i][p];
        }
        __syncthreads();

        if (tid < 128) {
            float gi = gps[0][     eu][eb] + gps[1][     eu][eb] + gps[2][     eu][eb] + gps[3][     eu][eb] + xp0;
            float gf = gps[0][16 + eu][eb] + gps[1][16 + eu][eb] + gps[2][16 + eu][eb] + gps[3][16 + eu][eb] + xp1;
            float gc = gps[0][32 + eu][eb] + gps[1][32 + eu][eb] + gps[2][32 + eu][eb] + gps[3][32 + eu][eb] + xp2;
            float go = gps[0][48 + eu][eb] + gps[1][48 + eu][eb] + gps[2][48 + eu][eb] + gps[3][48 + eu][eb] + xp3;
            float i_ = 1.f / (1.f + __expf(-gi));
            float f_ = 1.f / (1.f + __expf(-gf));
            float gg = tanhf(gc);
            float o_ = 1.f / (1.f + __expf(-go));
            c_reg = f_ * c_reg + i_ * gg;
            float hv = o_ * tanhf(c_reg);
            g_hx[t & 1][grp][(cig * 16 + eu) * GBATCH + eb] = hv;
            hout[((size_t)(grp * GBATCH + eb) * LL + t) * HID + cig * 16 + eu] = hv;
        }

        if (t == LL - 1) break;

        // ---- per-group release/acquire barrier ----
        __syncthreads();                       // epilogue global writes done (CTA-wide)
        if (tid == 0) {
            if (atom_add_release(cntp, 1u) == (GCTAS - 1u)) {
                *cntp = 0u;                    // ordered before the release below
                st_release(php, (unsigned)(t + 1));
            }
        }
        while (ld_acquire(php) < (unsigned)(t + 1)) {}
    }
}

// ---------------- att[m] = attT[m,:] . sim_W --------------------------------
__global__ void att_reduce(const float* __restrict__ attT,
                           const float* __restrict__ simW,
                           float* __restrict__ att)
{
    int gid  = blockIdx.x * blockDim.x + threadIdx.x;
    int row  = gid >> 5;
    int lane = threadIdx.x & 31;
    if (row >= BLROWS) return;
    float v = 0.f;
    for (int a = lane; a < ATTD; a += 32)
        v += attT[(size_t)row * ATTD + a] * simW[a];
    #pragma unroll
    for (int o = 16; o; o >>= 1) v += __shfl_down_sync(0xffffffffu, v, o);
    if (lane == 0) att[row] = v;
}

// ---------------- causal attention via online-softmax prefix scan -----------
// grid (BB, 4), block 128. Depth-8 register prefetch ring breaks the serial
// DRAM latency on the out[] loads; MUFU exp/div on the scan chain.
__global__ void attn_scan(const float* __restrict__ att,
                          const float* __restrict__ out,
                          float* __restrict__ finalbuf)
{
    int b = blockIdx.x;
    int h = blockIdx.y * 128 + threadIdx.x;
    __shared__ float s_att[LL];
    for (int i = threadIdx.x; i < LL; i += 128) s_att[i] = att[(size_t)b * LL + i];
    __syncthreads();

    const float* ob = out      + (size_t)b * LL * HID + h;
    float*       fb = finalbuf + (size_t)b * LL * (2 * HID) + h;

    float pre[8];
    #pragma unroll
    for (int j = 0; j < 8; j++) pre[j] = ob[(size_t)j * HID];

    float m = -1e30f, den = 0.f, num = 0.f, cum = 0.f;
    for (int i0 = 0; i0 < LL; i0 += 8) {
        #pragma unroll
        for (int j = 0; j < 8; j++) {
            int i = i0 + j;
            float ov = pre[j];
            int ip = i + 8;
            if (ip < LL) pre[j] = ob[(size_t)ip * HID];
            float s     = s_att[i];
            float mnew  = fmaxf(m, s);
            float scale = __expf(m - mnew);
            float alpha = __expf(s - mnew);
            num = num * scale + alpha * ov;
            den = den * scale + alpha;
            m   = mnew;
            fb[(size_t)i * (2 * HID)]       = cum;   // attn_cum_1 (exclusive)
            fb[(size_t)i * (2 * HID) + HID] = ov;    // out
            cum += __fdividef(num, den);
        }
    }
}

// ---------------- launch -----------------------------------------------------
extern "C" void kernel_launch(void* const* d_in, const int* in_sizes, int n_in,
                              void* d_out, int out_size)
{
    const int*   skill        = (const int*)  d_in[0];
    const int*   answer       = (const int*)  d_in[1];
    const float* skill_table  = (const float*)d_in[2];
    const float* answer_table = (const float*)d_in[3];
    const float* W_ih         = (const float*)d_in[4];
    const float* W_hh         = (const float*)d_in[5];
    const float* b_ih         = (const float*)d_in[6];
    const float* b_hh         = (const float*)d_in[7];
    const float* mlp_W        = (const float*)d_in[8];
    const float* mlp_b        = (const float*)d_in[9];
    const float* sim_W        = (const float*)d_in[10];
    const float* fc_W         = (const float*)d_in[11];
    const float* fc_b         = (const float*)d_in[12];
    float* outp = (float*)d_out;

    float *p_sae, *p_xpre, *p_hout, *p_attT, *p_att, *p_final;
    cudaGetSymbolAddress((void**)&p_sae,   g_sae);
    cudaGetSymbolAddress((void**)&p_xpre,  g_xpre);
    cudaGetSymbolAddress((void**)&p_hout,  g_hout);
    cudaGetSymbolAddress((void**)&p_attT,  g_attT);
    cudaGetSymbolAddress((void**)&p_att,   g_att);
    cudaGetSymbolAddress((void**)&p_final, g_final);

    // 1) embeddings -> sae (also resets LSTM barrier state for graph replays)
    {
        int total = BLROWS * 128;
        embed_kernel<<<total / 256, 256>>>(skill, answer, skill_table, answer_table);
    }

    // 2) x_pre = sae @ W_ih^T + (b_ih + b_hh)      [tf32 tensor cores]
    {
        dim3 grid(G4 / 128, BLROWS / 128);
        tf32gemm_nt<0><<<grid, 256>>>(p_sae, W_ih, b_ih, b_hh, p_xpre,
                                      BLROWS, G4, HID);
    }

    // 3) LSTM recurrence (4 independent groups of 32 CTAs)
    {
        const int smem = (64 * 520 + 512 * GBATCH) * (int)sizeof(float);  // 149504
        cudaFuncSetAttribute(lstm_kernel,
                             cudaFuncAttributeMaxDynamicSharedMemorySize, smem);
        lstm_kernel<<<NGRP * GCTAS, 256, smem>>>(p_xpre, W_hh, p_hout);
    }

    // 4) attT = tanh(out @ mlp_W^T + mlp_b)        [tf32 tensor cores]
    {
        dim3 grid((ATTD + 127) / 128, BLROWS / 128);
        tf32gemm_nt<1><<<grid, 256>>>(p_hout, mlp_W, mlp_b, nullptr, p_attT,
                                      BLROWS, ATTD, HID);
    }

    // 5) att = attT . sim_W
    att_reduce<<<(BLROWS * 32) / 256, 256>>>(p_attT, sim_W, p_att);

    // 6) online-softmax prefix scan -> final = [attn_cum_1, out]
    {
        dim3 grid(BB, 4);
        attn_scan<<<grid, 128>>>(p_att, p_hout, p_final);
    }

    // 7) res = sigmoid(final @ fc_W^T + fc_b)      [tf32 tensor cores]
    {
        dim3 grid((NUMC + 127) / 128, BLROWS / 128);
        tf32gemm_nt<2><<<grid, 256>>>(p_final, fc_W, fc_b, nullptr, outp,
                                      BLROWS, NUMC, 2 * HID);
    }
}